// round 6
// baseline (speedup 1.0000x reference)
#include <cuda_runtime.h>
#include <math.h>
#include <stdint.h>

typedef unsigned long long ull;

// ---------------- problem constants ----------------
#define BATCH 32
#define TT    1024
#define FF    40
#define HH    256
#define G4    1024      // 4*H
#define T2    342
#define V1    30        // V+1

// output layout (float32)
#define OFF_CTC_S 0
#define OFF_LEN_S 328320
#define OFF_CTC_C 328352
#define OFF_LEN_C 656672
#define OFF_CLOSE 656704

// ---------------- scratch (device globals; no allocation) ----------------
__device__ float g_xz[2u*32u*1024u*1024u];      // 256 MB: xz for lstm0; reused (smaller) for lstm1
__device__ float g_pool[2*32*342*256];          // pooled lstm0 output
__device__ float g_hA[2*32*342*256];            // lstm1 pass A output
__device__ float g_hB[2*32*342*256];            // lstm1 pass B output

// ---------------- cluster / mbarrier helpers ----------------
__device__ __forceinline__ uint32_t smem_u32(const void* p) {
    uint32_t a;
    asm("{ .reg .u64 t; cvta.to.shared.u64 t, %1; cvt.u32.u64 %0, t; }" : "=r"(a) : "l"(p));
    return a;
}
__device__ __forceinline__ uint32_t mapa_rank(uint32_t addr, uint32_t rank) {
    uint32_t r;
    asm("mapa.shared::cluster.u32 %0, %1, %2;" : "=r"(r) : "r"(addr), "r"(rank));
    return r;
}
__device__ __forceinline__ void mbar_init(uint32_t addr, uint32_t count) {
    asm volatile("mbarrier.init.shared.b64 [%0], %1;" :: "r"(addr), "r"(count) : "memory");
}
__device__ __forceinline__ void mbar_expect(uint32_t addr, uint32_t tx) {
    asm volatile("mbarrier.arrive.expect_tx.shared.b64 _, [%0], %1;" :: "r"(addr), "r"(tx) : "memory");
}
__device__ __forceinline__ void mbar_wait(uint32_t addr, uint32_t parity) {
    asm volatile(
        "{\n\t.reg .pred P;\n"
        "LW_%=:\n\t"
        "mbarrier.try_wait.parity.acquire.cluster.shared::cta.b64 P, [%0], %1, 0x989680;\n\t"
        "@P bra LD_%=;\n\t"
        "bra LW_%=;\n"
        "LD_%=:\n\t}"
        :: "r"(addr), "r"(parity) : "memory");
}
// bulk SMEM->peer-SMEM copy, completes (tx bytes) on the peer's mbarrier
__device__ __forceinline__ void bulk_copy_s2c(uint32_t dst, uint32_t src, uint32_t bytes, uint32_t rmbar) {
    asm volatile("cp.async.bulk.shared::cluster.shared::cta.mbarrier::complete_tx::bytes [%0], [%1], %2, [%3];"
                 :: "r"(dst), "r"(src), "r"(bytes), "r"(rmbar) : "memory");
}
__device__ __forceinline__ void fence_proxy_async_sc() {
    asm volatile("fence.proxy.async.shared::cta;" ::: "memory");
}

// fast sigmoid / tanh (EX2 + RCP based; ~1e-6 rel err)
__device__ __forceinline__ float fsigm(float x) {
    return __fdividef(1.f, 1.f + __expf(-x));
}
__device__ __forceinline__ float ftanh_(float x) {
    return __fdividef(2.f, 1.f + __expf(-2.f * x)) - 1.f;
}

// ---------------- tiled GEMM with bias: out[M,1024] = A[M,K] @ W[K,1024] + b ----------------
__global__ __launch_bounds__(256) void gemm_bias_kernel(
    const float* __restrict__ Aext,
    const float* __restrict__ W0, const float* __restrict__ W1,
    const float* __restrict__ b0, const float* __restrict__ b1,
    int M, int K, int mode)
{
    const int branch = blockIdx.z;
    const float* W = branch ? W1 : W0;
    const float* bias = branch ? b1 : b0;

    const float* A;
    float* out;
    if (mode == 0) {
        A = Aext;
        out = g_xz + (size_t)branch * (32u*1024u*1024u);
    } else if (mode == 1) {
        A = g_pool + (size_t)branch * (32*342*256);
        out = g_xz + (size_t)branch * (32u*342u*1024u);
    } else {
        A = g_hA + (size_t)branch * (32*342*256);
        out = g_xz + (size_t)branch * (32u*342u*1024u);
    }

    __shared__ float As[64][17];
    __shared__ float Bs[16][128];

    const int tid = threadIdx.x;
    const int tr = tid >> 5;
    const int tc = tid & 31;
    const int m0 = blockIdx.y * 64;
    const int n0 = blockIdx.x * 128;

    float acc[8][4];
    #pragma unroll
    for (int i = 0; i < 8; i++)
        #pragma unroll
        for (int j = 0; j < 4; j++) acc[i][j] = 0.f;

    for (int k0 = 0; k0 < K; k0 += 16) {
        #pragma unroll
        for (int i = tid; i < 1024; i += 256) {
            int m = i >> 4, k = i & 15;
            float v = 0.f;
            if (k0 + k < K) {
                v = A[(size_t)(m0 + m) * K + k0 + k];
                if (mode == 0) v = fminf(3.f, fmaxf(-3.f, v));
            }
            As[m][k] = v;
        }
        #pragma unroll
        for (int i = tid; i < 2048; i += 256) {
            int k = i >> 7, n = i & 127;
            Bs[k][n] = (k0 + k < K) ? W[(size_t)(k0 + k) * 1024 + n0 + n] : 0.f;
        }
        __syncthreads();
        #pragma unroll
        for (int k = 0; k < 16; k++) {
            float4 bv = *(const float4*)&Bs[k][tc * 4];
            #pragma unroll
            for (int i = 0; i < 8; i++) {
                float a = As[tr * 8 + i][k];
                acc[i][0] += a * bv.x;
                acc[i][1] += a * bv.y;
                acc[i][2] += a * bv.z;
                acc[i][3] += a * bv.w;
            }
        }
        __syncthreads();
    }
    float4 bv = *(const float4*)&bias[n0 + tc * 4];
    #pragma unroll
    for (int i = 0; i < 8; i++) {
        float4 r = make_float4(acc[i][0] + bv.x, acc[i][1] + bv.y,
                               acc[i][2] + bv.z, acc[i][3] + bv.w);
        *(float4*)&out[(size_t)(m0 + tr * 8 + i) * 1024 + n0 + tc * 4] = r;
    }
}

// ---------------- persistent recurrent LSTM kernel (8-CTA cluster gangs) ----------------
// grid = 128 blocks: blockIdx.x = gang*8 + cg; gang = branch*8 + bg; cg = cluster rank.
// Block owns 32 hidden units (j0 = cg*32), all 4 gates (128 local cols), all 256 k rows.
// 256 threads: warp kg (0..7) owns k rows kg*32..+31; lane owns local cols lane*4..+3.
// h exchanged via 512B cp.async.bulk SMEM->SMEM copies + 2 mbarriers (step parity).
// h layout: h_s[par][src_cg][b][jj]  (slice from CTA src_cg is contiguous 512B)
__global__ void __launch_bounds__(256, 1) __cluster_dims__(8, 1, 1)
lstm_rec_kernel(
    const float* __restrict__ Wr0, const float* __restrict__ Wr1,
    const int* __restrict__ x_len, int T, int mode)
{
    const int blk = blockIdx.x;
    const int gang = blk >> 3;
    const int cg = blk & 7;
    const int branch = gang >> 3;
    const int bg = gang & 7;
    const int j0 = cg * 32;
    const float* Wr = branch ? Wr1 : Wr0;

    const int tid = threadIdx.x;
    const int kg = tid >> 5;          // warp = k-group 0..7 (== source cg of that h slice)
    const int lane = tid & 31;

    __shared__ __align__(16) float h_s[2][8][4][32];   // 8KB  [par][src][b][jj]
    __shared__ __align__(16) float hstage[2][4][32];   // 1KB  own h slice staging
    __shared__ float ps[8][4][128];                    // 16KB partial sums
    __shared__ float zs[4][128];                       // 2KB  reduced z
    __shared__ __align__(8) ull mbar_s[2];

    // ---- mbarrier init + initial expects ----
    const uint32_t mb0 = smem_u32(&mbar_s[0]);
    if (tid == 0) {
        mbar_init(mb0, 1);
        mbar_init(mb0 + 8, 1);
    }
    __syncthreads();
    if (tid == 0) {
        mbar_expect(mb0, 4096);       // phase 0 of mbar0: h(2)
        mbar_expect(mb0 + 8, 4096);   // phase 0 of mbar1: h(1)
    }

    // ---- zero h(0) buffer ----
    {
        float* p = &h_s[0][0][0][0];
        #pragma unroll
        for (int i = tid; i < 1024; i += 256) p[i] = 0.f;
    }

    // ---- load weight slice into registers (once): 32 k x 4 cols ----
    float4 wreg[32];
    {
        const int c0 = lane * 4;
        const int gate = c0 >> 5;
        const int jj = c0 & 31;
        const float* wb = Wr + gate * 256 + j0 + jj;
        const int kbase = kg * 32;
        #pragma unroll
        for (int kk = 0; kk < 32; kk++) {
            const float* wr = wb + (size_t)(kbase + kk) * 1024;
            wreg[kk] = make_float4(wr[0], wr[1], wr[2], wr[3]);
        }
    }

    // ---- gate role (tid < 128): gb = tid>>5, gjj = tid&31 ----
    const int gb = tid >> 5;
    const int gjj = tid & 31;
    float cst = 0.f;
    float poolm = __int_as_float(0xff800000);
    int mylen = 0, b_glob = 0;
    if (tid < 128) {
        b_glob = bg * 4 + gb;
        int xl = x_len[b_glob];
        mylen = (mode == 0) ? xl : (xl + 2) / 3;
    }

    // peer base addresses (8 ranks)
    uint32_t peer_h8 = 0, peer_mb8 = 0;
    const uint32_t hstage_a = smem_u32(&hstage[0][0][0]);
    if (tid < 8) {
        peer_h8 = mapa_rank(smem_u32(&h_s[0][0][0][0]), tid);
        peer_mb8 = mapa_rank(mb0, tid);
    }

    // reduce role: 2 slots per thread over 512 = 4b x 128c
    const int rb1 = tid >> 7, rc1 = tid & 127;
    const int rb2 = (tid + 256) >> 7, rc2 = (tid + 256) & 127;
    const int Tstride = (mode == 0) ? 1024 : 342;
    const size_t xcol1 = (size_t)((rc1 >> 5) << 8) + j0 + (rc1 & 31);
    const size_t xcol2 = (size_t)((rc2 >> 5) << 8) + j0 + (rc2 & 31);
    const float* xz = g_xz + (size_t)branch * 32u * (size_t)Tstride * 1024u;
    const float* xzp1 = xz + (size_t)(bg * 4 + rb1) * Tstride * 1024u + xcol1;
    const float* xzp2 = xz + (size_t)(bg * 4 + rb2) * Tstride * 1024u + xcol2;

    float* poolp = g_pool + ((size_t)(branch * 32 + b_glob) * 342) * 256 + j0 + gjj;
    float* hop = ((mode == 1) ? g_hA : g_hB) + ((size_t)(branch * 32 + b_glob) * 342) * 256 + j0 + gjj;

    __syncthreads();
    // cluster sync: mbarriers + expects visible before any peer bulk copy
    asm volatile("barrier.cluster.arrive.aligned;" ::: "memory");
    asm volatile("barrier.cluster.wait.aligned;" ::: "memory");

    uint32_t phase0 = 0, phase1 = 0;

    for (int t = 0; t < T; t++) {
        const int par = t & 1;
        const int par1 = par ^ 1;

        // prefetch xz for this step (independent of h)
        float xz1v = xzp1[(size_t)t * 1024];
        float xz2v = xzp2[(size_t)t * 1024];

        // ---- wait for h(t), re-arm for h(t+2) ----
        if (t > 0) {
            if (par) {
                mbar_wait(mb0 + 8, phase1);
                phase1 ^= 1;
                if (tid == 0) mbar_expect(mb0 + 8, 4096);
            } else {
                mbar_wait(mb0, phase0);
                phase0 ^= 1;
                if (tid == 0) mbar_expect(mb0, 4096);
            }
        }

        // ---- GEMM: partial z over owned 32 k rows (slice kg), 4 cols, 4 batches ----
        #pragma unroll
        for (int b = 0; b < 4; b++) {
            float ax = 0.f, ay = 0.f, az = 0.f, aw = 0.f;
            #pragma unroll
            for (int kk4 = 0; kk4 < 8; kk4++) {
                float4 h4 = *(const float4*)&h_s[par][kg][b][4 * kk4];
                float4 w;
                w = wreg[4*kk4+0]; ax += h4.x*w.x; ay += h4.x*w.y; az += h4.x*w.z; aw += h4.x*w.w;
                w = wreg[4*kk4+1]; ax += h4.y*w.x; ay += h4.y*w.y; az += h4.y*w.z; aw += h4.y*w.w;
                w = wreg[4*kk4+2]; ax += h4.z*w.x; ay += h4.z*w.y; az += h4.z*w.z; aw += h4.z*w.w;
                w = wreg[4*kk4+3]; ax += h4.w*w.x; ay += h4.w*w.y; az += h4.w*w.z; aw += h4.w*w.w;
            }
            *(float4*)&ps[kg][b][4 * lane] = make_float4(ax, ay, az, aw);
        }
        __syncthreads();

        // ---- reduce across 8 k-groups + add xz ----
        float z1 = xz1v, z2 = xz2v;
        #pragma unroll
        for (int q = 0; q < 8; q++) {
            z1 += ps[q][rb1][rc1];
            z2 += ps[q][rb2][rc2];
        }
        zs[rb1][rc1] = z1;
        zs[rb2][rc2] = z2;
        __syncthreads();

        // ---- gates / state / stage h(t+1) ----
        if (tid < 128) {
            float zi = zs[gb][gjj];
            float zf = zs[gb][32 + gjj];
            float zg = zs[gb][64 + gjj];
            float zo = zs[gb][96 + gjj];
            float iv = fsigm(zi);
            float fv = fsigm(zf);
            float gv = ftanh_(zg);
            float ov = fsigm(zo);
            float cn = fv * cst + iv * gv;
            float hn = ov * ftanh_(cn);
            bool m = (t < mylen);
            float hp = h_s[par][cg][gb][gjj];
            float hv = m ? hn : hp;
            cst = m ? cn : cst;

            // outputs
            if (mode == 0) {
                poolm = fmaxf(poolm, hv);
                if ((t % 3) == 1) {
                    poolp[(size_t)(t / 3) * 256] = poolm;
                    poolm = __int_as_float(0xff800000);
                }
            } else {
                hop[(size_t)t * 256] = hv;
            }

            hstage[par1][gb][gjj] = hv;
        }
        __syncthreads();

        // ---- one 512B bulk copy to each of 8 cluster CTAs ----
        if (t + 1 < T && tid < 8) {
            fence_proxy_async_sc();
            const uint32_t dstoff = (uint32_t)((par1 * 8 + cg) * 512);
            bulk_copy_s2c(peer_h8 + dstoff, hstage_a + par1 * 512, 512,
                          peer_mb8 + (uint32_t)(par1 * 8));
        }
    }

    // flush final pool window (covers t = 1022,1023)
    if (mode == 0 && tid < 128) {
        poolp[341u * 256] = poolm;
    }
}

// ---------------- CTC projection: out = hB @ ctc_w + ctc_b ----------------
__global__ __launch_bounds__(256) void ctc_kernel(
    const float* __restrict__ W, const float* __restrict__ bias, float* __restrict__ out)
{
    __shared__ float As[8][256];
    const int r0 = blockIdx.x * 8;
    for (int i = threadIdx.x; i < 2048; i += 256) {
        As[i >> 8][i & 255] = g_hB[(size_t)r0 * 256 + i];
    }
    __syncthreads();
    if (threadIdx.x < 240) {
        const int rl = threadIdx.x / 30;
        const int n = threadIdx.x % 30;
        float acc = bias[n];
        #pragma unroll 8
        for (int k = 0; k < 256; k++) acc += As[rl][k] * __ldg(&W[k * 30 + n]);
        const int r = r0 + rl;
        const int branch = r / 10944;
        const int idx = r - branch * 10944;
        const size_t o = (branch ? (size_t)OFF_CTC_C : (size_t)OFF_CTC_S) + (size_t)idx * 30 + n;
        out[o] = acc;
    }
}

// ---------------- lens + close ----------------
__global__ void finalize_kernel(const int* __restrict__ x_len, float* __restrict__ out)
{
    const int b = blockIdx.x;
    const float* s = out + OFF_CTC_S + (size_t)b * 10260;
    const float* c = out + OFF_CTC_C + (size_t)b * 10260;
    int ok = 1;
    for (int i = threadIdx.x; i < 10260; i += 256) {
        if (!(fabsf(s[i] - c[i]) < 1e-5f)) ok = 0;
    }
    int allok = __syncthreads_and(ok);
    if (threadIdx.x == 0) {
        float len = (float)((x_len[b] + 2) / 3);
        out[OFF_LEN_S + b] = len;
        out[OFF_LEN_C + b] = len;
        out[OFF_CLOSE + b] = allok ? 1.f : 0.f;
    }
}

// ---------------- launch ----------------
extern "C" void kernel_launch(void* const* d_in, const int* in_sizes, int n_in,
                              void* d_out, int out_size)
{
    const float* x      = (const float*)d_in[0];
    const int*   x_len  = (const int*)  d_in[1];
    const float* ws0_k  = (const float*)d_in[2];
    const float* ws0_r  = (const float*)d_in[3];
    const float* ws0_b  = (const float*)d_in[4];
    const float* ws1_k  = (const float*)d_in[5];
    const float* ws1_r  = (const float*)d_in[6];
    const float* ws1_b  = (const float*)d_in[7];
    const float* wc0_k  = (const float*)d_in[8];
    const float* wc0_r  = (const float*)d_in[9];
    const float* wc0_b  = (const float*)d_in[10];
    const float* wc1_k  = (const float*)d_in[11];
    const float* wc1_r  = (const float*)d_in[12];
    const float* wc1_b  = (const float*)d_in[13];
    const float* ctc_w  = (const float*)d_in[14];
    const float* ctc_b  = (const float*)d_in[15];
    float* out = (float*)d_out;

    // xz0 = clip(x) @ Wk0 + b0   (M = 32*1024, K = 40)
    gemm_bias_kernel<<<dim3(8, 512, 2), 256>>>(x, ws0_k, wc0_k, ws0_b, wc0_b, 32768, 40, 0);

    // lstm0 + fused maxpool3
    lstm_rec_kernel<<<128, 256>>>(ws0_r, wc0_r, x_len, 1024, 0);

    // xz1A = pooled @ Wk1 + b1   (M = 32*342, K = 256)
    gemm_bias_kernel<<<dim3(8, 171, 2), 256>>>(nullptr, ws1_k, wc1_k, ws1_b, wc1_b, 10944, 256, 1);

    // lstm1 pass A
    lstm_rec_kernel<<<128, 256>>>(ws1_r, wc1_r, x_len, 342, 1);

    // xz1B = hA @ Wk1 + b1
    gemm_bias_kernel<<<dim3(8, 171, 2), 256>>>(nullptr, ws1_k, wc1_k, ws1_b, wc1_b, 10944, 256, 2);

    // lstm1 pass B
    lstm_rec_kernel<<<128, 256>>>(ws1_r, wc1_r, x_len, 342, 2);

    // CTC projection for both branches
    ctc_kernel<<<2736, 256>>>(ctc_w, ctc_b, out);

    // lens + close
    finalize_kernel<<<32, 256>>>(x_len, out);
}

// round 7
// speedup vs baseline: 1.0285x; 1.0285x over previous
#include <cuda_runtime.h>
#include <math.h>
#include <stdint.h>

typedef unsigned long long ull;

// output layout (float32)
#define OFF_CTC_S 0
#define OFF_LEN_S 328320
#define OFF_CTC_C 328352
#define OFF_LEN_C 656672
#define OFF_CLOSE 656704

// ---------------- scratch (device globals; no allocation) ----------------
__device__ float g_xz[2u*32u*1024u*1024u];      // xz for lstm0; reused (smaller) for lstm1
__device__ float g_pool[2*32*342*256];          // pooled lstm0 output
__device__ float g_hA[2*32*342*256];            // lstm1 pass A output
__device__ float g_hB[2*32*342*256];            // lstm1 pass B output

// ---------------- cluster / mbarrier helpers ----------------
__device__ __forceinline__ uint32_t smem_u32(const void* p) {
    uint32_t a;
    asm("{ .reg .u64 t; cvta.to.shared.u64 t, %1; cvt.u32.u64 %0, t; }" : "=r"(a) : "l"(p));
    return a;
}
__device__ __forceinline__ uint32_t mapa_rank(uint32_t addr, uint32_t rank) {
    uint32_t r;
    asm("mapa.shared::cluster.u32 %0, %1, %2;" : "=r"(r) : "r"(addr), "r"(rank));
    return r;
}
__device__ __forceinline__ void mbar_init(uint32_t addr, uint32_t count) {
    asm volatile("mbarrier.init.shared.b64 [%0], %1;" :: "r"(addr), "r"(count) : "memory");
}
__device__ __forceinline__ void mbar_expect(uint32_t addr, uint32_t tx) {
    asm volatile("mbarrier.arrive.expect_tx.shared.b64 _, [%0], %1;" :: "r"(addr), "r"(tx) : "memory");
}
__device__ __forceinline__ void mbar_wait(uint32_t addr, uint32_t parity) {
    asm volatile(
        "{\n\t.reg .pred P;\n"
        "LW_%=:\n\t"
        "mbarrier.try_wait.parity.acquire.cluster.shared::cta.b64 P, [%0], %1, 0x989680;\n\t"
        "@P bra LD_%=;\n\t"
        "bra LW_%=;\n"
        "LD_%=:\n\t}"
        :: "r"(addr), "r"(parity) : "memory");
}
__device__ __forceinline__ void st_async_b32(uint32_t raddr, float v, uint32_t rmbar) {
    asm volatile("st.async.shared::cluster.mbarrier::complete_tx::bytes.b32 [%0], %1, [%2];"
                 :: "r"(raddr), "f"(v), "r"(rmbar) : "memory");
}

// fast sigmoid / tanh (EX2 + RCP based; ~1e-6 rel err)
__device__ __forceinline__ float fsigm(float x) {
    return __fdividef(1.f, 1.f + __expf(-x));
}
__device__ __forceinline__ float ftanh_(float x) {
    return __fdividef(2.f, 1.f + __expf(-2.f * x)) - 1.f;
}

__device__ __forceinline__ void fma_bc(float4& a, float hs, const float4 w) {
    a.x = fmaf(hs, w.x, a.x);
    a.y = fmaf(hs, w.y, a.y);
    a.z = fmaf(hs, w.z, a.z);
    a.w = fmaf(hs, w.w, a.w);
}

// ---------------- tiled GEMM with bias: out[M,1024] = A[M,K] @ W[K,1024] + b ----------------
__global__ __launch_bounds__(256) void gemm_bias_kernel(
    const float* __restrict__ Aext,
    const float* __restrict__ W0, const float* __restrict__ W1,
    const float* __restrict__ b0, const float* __restrict__ b1,
    int M, int K, int mode)
{
    const int branch = blockIdx.z;
    const float* W = branch ? W1 : W0;
    const float* bias = branch ? b1 : b0;

    const float* A;
    float* out;
    if (mode == 0) {
        A = Aext;
        out = g_xz + (size_t)branch * (32u*1024u*1024u);
    } else if (mode == 1) {
        A = g_pool + (size_t)branch * (32*342*256);
        out = g_xz + (size_t)branch * (32u*342u*1024u);
    } else {
        A = g_hA + (size_t)branch * (32*342*256);
        out = g_xz + (size_t)branch * (32u*342u*1024u);
    }

    __shared__ float As[64][17];
    __shared__ float Bs[16][128];

    const int tid = threadIdx.x;
    const int tr = tid >> 5;
    const int tc = tid & 31;
    const int m0 = blockIdx.y * 64;
    const int n0 = blockIdx.x * 128;

    float acc[8][4];
    #pragma unroll
    for (int i = 0; i < 8; i++)
        #pragma unroll
        for (int j = 0; j < 4; j++) acc[i][j] = 0.f;

    for (int k0 = 0; k0 < K; k0 += 16) {
        #pragma unroll
        for (int i = tid; i < 1024; i += 256) {
            int m = i >> 4, k = i & 15;
            float v = 0.f;
            if (k0 + k < K) {
                v = A[(size_t)(m0 + m) * K + k0 + k];
                if (mode == 0) v = fminf(3.f, fmaxf(-3.f, v));
            }
            As[m][k] = v;
        }
        #pragma unroll
        for (int i = tid; i < 2048; i += 256) {
            int k = i >> 7, n = i & 127;
            Bs[k][n] = (k0 + k < K) ? W[(size_t)(k0 + k) * 1024 + n0 + n] : 0.f;
        }
        __syncthreads();
        #pragma unroll
        for (int k = 0; k < 16; k++) {
            float4 bv = *(const float4*)&Bs[k][tc * 4];
            #pragma unroll
            for (int i = 0; i < 8; i++) {
                float a = As[tr * 8 + i][k];
                acc[i][0] += a * bv.x;
                acc[i][1] += a * bv.y;
                acc[i][2] += a * bv.z;
                acc[i][3] += a * bv.w;
            }
        }
        __syncthreads();
    }
    float4 bv = *(const float4*)&bias[n0 + tc * 4];
    #pragma unroll
    for (int i = 0; i < 8; i++) {
        float4 r = make_float4(acc[i][0] + bv.x, acc[i][1] + bv.y,
                               acc[i][2] + bv.z, acc[i][3] + bv.w);
        *(float4*)&out[(size_t)(m0 + tr * 8 + i) * 1024 + n0 + tc * 4] = r;
    }
}

// ---------------- persistent dual-chain recurrent LSTM kernel ----------------
// grid = 64 CTAs = 8 gangs (batch groups) x 8 CTAs (cluster). cg = rank, owns 32 hidden units.
// Each CTA runs BOTH branches: chain S (branch 0) weights in registers,
// chain C (branch 1) weights in SMEM. Chains alternate in the step loop so each
// chain's DSMEM h-exchange latency is hidden under the other chain's compute.
// h exchange: per-gate-thread st.async.b32 x8 + per-chain/per-parity mbarriers.
// h layout (both chains): h[par][b][k] (k = global hidden index 0..255).
#define SM_WC    0          // chain C weights: float4 [256][32]  (128 KB)
#define SM_HS    131072     // chain S h: [2][4][256] floats      (8 KB)
#define SM_HC    139264     // chain C h                           (8 KB)
#define SM_PSS   147456     // chain S partials: [8][4][128]       (16 KB)
#define SM_PSC   163840     // chain C partials                    (16 KB)
#define SM_MBAR  180224     // 4 mbarriers: S-p0, S-p1, C-p0, C-p1
#define SM_TOTAL 180256

extern __shared__ __align__(16) char smdyn[];

__global__ void __launch_bounds__(256, 1) __cluster_dims__(8, 1, 1)
lstm_rec_kernel(
    const float* __restrict__ Wr0, const float* __restrict__ Wr1,
    const int* __restrict__ x_len, int T, int mode)
{
    float* wc  = (float*)(smdyn + SM_WC);
    float* hS  = (float*)(smdyn + SM_HS);
    float* hC  = (float*)(smdyn + SM_HC);
    float* psS = (float*)(smdyn + SM_PSS);
    float* psC = (float*)(smdyn + SM_PSC);

    const int cg = blockIdx.x & 7;       // cluster rank / hidden-column group
    const int bg = blockIdx.x >> 3;      // batch group (4 batches)
    const int j0 = cg * 32;
    const int tid = threadIdx.x;
    const int kg = tid >> 5;             // warp = k-group 0..7
    const int lane = tid & 31;
    const int kbase = kg * 32;

    const uint32_t mbb = smem_u32(smdyn + SM_MBAR);
    if (tid == 0) {
        mbar_init(mbb + 0, 1);  mbar_init(mbb + 8, 1);
        mbar_init(mbb + 16, 1); mbar_init(mbb + 24, 1);
    }
    __syncthreads();
    if (tid == 0) {
        mbar_expect(mbb + 0, 4096);  mbar_expect(mbb + 8, 4096);
        mbar_expect(mbb + 16, 4096); mbar_expect(mbb + 24, 4096);
    }

    // zero h(0) (parity 0) for both chains
    for (int i = tid; i < 1024; i += 256) { hS[i] = 0.f; hC[i] = 0.f; }

    // ---- chain S weights -> registers (32k x 4 cols per thread) ----
    float4 wreg[32];
    {
        const int c0 = lane * 4;
        const int gate = c0 >> 5;
        const int jj = c0 & 31;
        const float* wb = Wr0 + gate * 256 + j0 + jj;
        #pragma unroll
        for (int kk = 0; kk < 32; kk++) {
            const float* wr = wb + (size_t)(kbase + kk) * 1024;
            wreg[kk] = make_float4(wr[0], wr[1], wr[2], wr[3]);
        }
    }
    // ---- chain C weights -> SMEM: wc4[k][lane] (same column mapping) ----
    for (int idx = tid; idx < 8192; idx += 256) {
        int k = idx >> 5, l = idx & 31;
        int g2 = (l * 4) >> 5, j2 = (l * 4) & 31;
        const float* p = Wr1 + (size_t)k * 1024 + g2 * 256 + j0 + j2;
        ((float4*)wc)[idx] = make_float4(p[0], p[1], p[2], p[3]);
    }

    // ---- gate role (tid < 128): gb = batch-in-group, gjj = hidden-in-slice ----
    const int gb = tid >> 5;
    const int gjj = tid & 31;
    const float NEGINF = __int_as_float(0xff800000);
    float cstS = 0.f, cstC = 0.f;
    float poolmS = NEGINF, poolmC = NEGINF;
    int mylen = 0;
    const int Tstride = (mode == 0) ? 1024 : 342;
    const float *xzSp = nullptr, *xzCp = nullptr;
    float *poolpS = nullptr, *poolpC = nullptr, *hopS = nullptr, *hopC = nullptr;
    if (tid < 128) {
        const int b_glob = bg * 4 + gb;
        int xl = x_len[b_glob];
        mylen = (mode == 0) ? xl : (xl + 2) / 3;
        xzSp = g_xz + (size_t)b_glob * Tstride * 1024u + j0 + gjj;
        xzCp = xzSp + (size_t)32 * Tstride * 1024u;
        poolpS = g_pool + ((size_t)b_glob * 342) * 256 + j0 + gjj;
        poolpC = poolpS + (size_t)32 * 342 * 256;
        float* hbase = (mode == 1) ? g_hA : g_hB;
        hopS = hbase + ((size_t)b_glob * 342) * 256 + j0 + gjj;
        hopC = hopS + (size_t)32 * 342 * 256;
    }

    const uint32_t hS_a = smem_u32(hS);
    const uint32_t hC_a = smem_u32(hC);

    __syncthreads();
    // cluster sync: mbarriers + expects + smem weights visible before any peer st.async
    asm volatile("barrier.cluster.arrive.aligned;" ::: "memory");
    asm volatile("barrier.cluster.wait.aligned;" ::: "memory");

    uint32_t phS0 = 0, phS1 = 0, phC0 = 0, phC1 = 0;

    for (int t = 0; t < T; t++) {
        const int par = t & 1;
        const int par1 = par ^ 1;

        // prefetch xz for both chains (gate threads; hidden behind waits)
        float xS0, xS1, xS2, xS3, xC0, xC1, xC2, xC3;
        if (tid < 128) {
            const float* p1 = xzSp + (size_t)t * 1024;
            xS0 = p1[0]; xS1 = p1[256]; xS2 = p1[512]; xS3 = p1[768];
            const float* p2 = xzCp + (size_t)t * 1024;
            xC0 = p2[0]; xC1 = p2[256]; xC2 = p2[512]; xC3 = p2[768];
        }

        // ================= chain S =================
        if (t > 0) {
            if (par) { mbar_wait(mbb + 8, phS1);  phS1 ^= 1; if (tid == 0) mbar_expect(mbb + 8, 4096); }
            else     { mbar_wait(mbb + 0, phS0);  phS0 ^= 1; if (tid == 0) mbar_expect(mbb + 0, 4096); }
        }
        // GEMM S: partial z over owned 32 k rows, 4 cols, 4 batches (reg weights)
        #pragma unroll
        for (int b = 0; b < 4; b++) {
            float4 acc = make_float4(0.f, 0.f, 0.f, 0.f);
            #pragma unroll
            for (int kk4 = 0; kk4 < 8; kk4++) {
                float4 h4 = *(const float4*)&hS[((par * 4 + b) << 8) + kbase + 4 * kk4];
                fma_bc(acc, h4.x, wreg[4 * kk4 + 0]);
                fma_bc(acc, h4.y, wreg[4 * kk4 + 1]);
                fma_bc(acc, h4.z, wreg[4 * kk4 + 2]);
                fma_bc(acc, h4.w, wreg[4 * kk4 + 3]);
            }
            *(float4*)&psS[((kg * 4 + b) << 7) + 4 * lane] = acc;
        }
        __syncthreads();
        // gates S (per-thread 8-way reduce over psS) + send + store
        if (tid < 128) {
            float zi = xS0, zf = xS1, zg = xS2, zo = xS3;
            #pragma unroll
            for (int q = 0; q < 8; q++) {
                const float* pp = &psS[((q * 4 + gb) << 7)];
                zi += pp[gjj]; zf += pp[32 + gjj]; zg += pp[64 + gjj]; zo += pp[96 + gjj];
            }
            float iv = fsigm(zi), fv = fsigm(zf), gv = ftanh_(zg), ov = fsigm(zo);
            float cn = fv * cstS + iv * gv;
            float hn = ov * ftanh_(cn);
            bool m = (t < mylen);
            float hp = hS[((par * 4 + gb) << 8) + j0 + gjj];
            float hv = m ? hn : hp;
            cstS = m ? cn : cstS;
            if (t + 1 < T) {
                const uint32_t off = (uint32_t)(((par1 * 4 + gb) << 8) + j0 + gjj) * 4u;
                const uint32_t moff = par1 ? 8u : 0u;
                #pragma unroll
                for (int r = 0; r < 8; r++)
                    st_async_b32(mapa_rank(hS_a + off, r), hv, mapa_rank(mbb + moff, r));
            }
            if (mode == 0) {
                poolmS = fmaxf(poolmS, hv);
                if ((t % 3) == 1) { poolpS[(size_t)(t / 3) * 256] = poolmS; poolmS = NEGINF; }
            } else {
                hopS[(size_t)t * 256] = hv;
            }
        }

        // ================= chain C =================
        if (t > 0) {
            if (par) { mbar_wait(mbb + 24, phC1); phC1 ^= 1; if (tid == 0) mbar_expect(mbb + 24, 4096); }
            else     { mbar_wait(mbb + 16, phC0); phC0 ^= 1; if (tid == 0) mbar_expect(mbb + 16, 4096); }
        }
        // GEMM C: weights streamed from SMEM (w reused across 4 batches)
        {
            float4 a0 = make_float4(0.f, 0.f, 0.f, 0.f);
            float4 a1 = a0, a2 = a0, a3 = a0;
            #pragma unroll
            for (int kk4 = 0; kk4 < 8; kk4++) {
                const float4 w0 = ((const float4*)wc)[(kbase + 4 * kk4 + 0) * 32 + lane];
                const float4 w1 = ((const float4*)wc)[(kbase + 4 * kk4 + 1) * 32 + lane];
                const float4 w2 = ((const float4*)wc)[(kbase + 4 * kk4 + 2) * 32 + lane];
                const float4 w3 = ((const float4*)wc)[(kbase + 4 * kk4 + 3) * 32 + lane];
                float4 h4;
                h4 = *(const float4*)&hC[((par * 4 + 0) << 8) + kbase + 4 * kk4];
                fma_bc(a0, h4.x, w0); fma_bc(a0, h4.y, w1); fma_bc(a0, h4.z, w2); fma_bc(a0, h4.w, w3);
                h4 = *(const float4*)&hC[((par * 4 + 1) << 8) + kbase + 4 * kk4];
                fma_bc(a1, h4.x, w0); fma_bc(a1, h4.y, w1); fma_bc(a1, h4.z, w2); fma_bc(a1, h4.w, w3);
                h4 = *(const float4*)&hC[((par * 4 + 2) << 8) + kbase + 4 * kk4];
                fma_bc(a2, h4.x, w0); fma_bc(a2, h4.y, w1); fma_bc(a2, h4.z, w2); fma_bc(a2, h4.w, w3);
                h4 = *(const float4*)&hC[((par * 4 + 3) << 8) + kbase + 4 * kk4];
                fma_bc(a3, h4.x, w0); fma_bc(a3, h4.y, w1); fma_bc(a3, h4.z, w2); fma_bc(a3, h4.w, w3);
            }
            *(float4*)&psC[((kg * 4 + 0) << 7) + 4 * lane] = a0;
            *(float4*)&psC[((kg * 4 + 1) << 7) + 4 * lane] = a1;
            *(float4*)&psC[((kg * 4 + 2) << 7) + 4 * lane] = a2;
            *(float4*)&psC[((kg * 4 + 3) << 7) + 4 * lane] = a3;
        }
        __syncthreads();
        // gates C + send + store
        if (tid < 128) {
            float zi = xC0, zf = xC1, zg = xC2, zo = xC3;
            #pragma unroll
            for (int q = 0; q < 8; q++) {
                const float* pp = &psC[((q * 4 + gb) << 7)];
                zi += pp[gjj]; zf += pp[32 + gjj]; zg += pp[64 + gjj]; zo += pp[96 + gjj];
            }
            float iv = fsigm(zi), fv = fsigm(zf), gv = ftanh_(zg), ov = fsigm(zo);
            float cn = fv * cstC + iv * gv;
            float hn = ov * ftanh_(cn);
            bool m = (t < mylen);
            float hp = hC[((par * 4 + gb) << 8) + j0 + gjj];
            float hv = m ? hn : hp;
            cstC = m ? cn : cstC;
            if (t + 1 < T) {
                const uint32_t off = (uint32_t)(((par1 * 4 + gb) << 8) + j0 + gjj) * 4u;
                const uint32_t moff = par1 ? 24u : 16u;
                #pragma unroll
                for (int r = 0; r < 8; r++)
                    st_async_b32(mapa_rank(hC_a + off, r), hv, mapa_rank(mbb + moff, r));
            }
            if (mode == 0) {
                poolmC = fmaxf(poolmC, hv);
                if ((t % 3) == 1) { poolpC[(size_t)(t / 3) * 256] = poolmC; poolmC = NEGINF; }
            } else {
                hopC[(size_t)t * 256] = hv;
            }
        }
    }

    // flush final pool window (covers t = 1022,1023)
    if (mode == 0 && tid < 128) {
        poolpS[341u * 256] = poolmS;
        poolpC[341u * 256] = poolmC;
    }
}

// ---------------- CTC projection: out = hB @ ctc_w + ctc_b ----------------
__global__ __launch_bounds__(256) void ctc_kernel(
    const float* __restrict__ W, const float* __restrict__ bias, float* __restrict__ out)
{
    __shared__ float As[8][256];
    const int r0 = blockIdx.x * 8;
    for (int i = threadIdx.x; i < 2048; i += 256) {
        As[i >> 8][i & 255] = g_hB[(size_t)r0 * 256 + i];
    }
    __syncthreads();
    if (threadIdx.x < 240) {
        const int rl = threadIdx.x / 30;
        const int n = threadIdx.x % 30;
        float acc = bias[n];
        #pragma unroll 8
        for (int k = 0; k < 256; k++) acc += As[rl][k] * __ldg(&W[k * 30 + n]);
        const int r = r0 + rl;
        const int branch = r / 10944;
        const int idx = r - branch * 10944;
        const size_t o = (branch ? (size_t)OFF_CTC_C : (size_t)OFF_CTC_S) + (size_t)idx * 30 + n;
        out[o] = acc;
    }
}

// ---------------- lens + close ----------------
__global__ void finalize_kernel(const int* __restrict__ x_len, float* __restrict__ out)
{
    const int b = blockIdx.x;
    const float* s = out + OFF_CTC_S + (size_t)b * 10260;
    const float* c = out + OFF_CTC_C + (size_t)b * 10260;
    int ok = 1;
    for (int i = threadIdx.x; i < 10260; i += 256) {
        if (!(fabsf(s[i] - c[i]) < 1e-5f)) ok = 0;
    }
    int allok = __syncthreads_and(ok);
    if (threadIdx.x == 0) {
        float len = (float)((x_len[b] + 2) / 3);
        out[OFF_LEN_S + b] = len;
        out[OFF_LEN_C + b] = len;
        out[OFF_CLOSE + b] = allok ? 1.f : 0.f;
    }
}

// ---------------- launch ----------------
extern "C" void kernel_launch(void* const* d_in, const int* in_sizes, int n_in,
                              void* d_out, int out_size)
{
    const float* x      = (const float*)d_in[0];
    const int*   x_len  = (const int*)  d_in[1];
    const float* ws0_k  = (const float*)d_in[2];
    const float* ws0_r  = (const float*)d_in[3];
    const float* ws0_b  = (const float*)d_in[4];
    const float* ws1_k  = (const float*)d_in[5];
    const float* ws1_r  = (const float*)d_in[6];
    const float* ws1_b  = (const float*)d_in[7];
    const float* wc0_k  = (const float*)d_in[8];
    const float* wc0_r  = (const float*)d_in[9];
    const float* wc0_b  = (const float*)d_in[10];
    const float* wc1_k  = (const float*)d_in[11];
    const float* wc1_r  = (const float*)d_in[12];
    const float* wc1_b  = (const float*)d_in[13];
    const float* ctc_w  = (const float*)d_in[14];
    const float* ctc_b  = (const float*)d_in[15];
    float* out = (float*)d_out;

    cudaFuncSetAttribute(lstm_rec_kernel,
                         cudaFuncAttributeMaxDynamicSharedMemorySize, SM_TOTAL);

    // xz0 = clip(x) @ Wk0 + b0   (M = 32*1024, K = 40)
    gemm_bias_kernel<<<dim3(8, 512, 2), 256>>>(x, ws0_k, wc0_k, ws0_b, wc0_b, 32768, 40, 0);

    // lstm0 (both branches interleaved) + fused maxpool3
    lstm_rec_kernel<<<64, 256, SM_TOTAL>>>(ws0_r, wc0_r, x_len, 1024, 0);

    // xz1A = pooled @ Wk1 + b1   (M = 32*342, K = 256)
    gemm_bias_kernel<<<dim3(8, 171, 2), 256>>>(nullptr, ws1_k, wc1_k, ws1_b, wc1_b, 10944, 256, 1);

    // lstm1 pass A
    lstm_rec_kernel<<<64, 256, SM_TOTAL>>>(ws1_r, wc1_r, x_len, 342, 1);

    // xz1B = hA @ Wk1 + b1
    gemm_bias_kernel<<<dim3(8, 171, 2), 256>>>(nullptr, ws1_k, wc1_k, ws1_b, wc1_b, 10944, 256, 2);

    // lstm1 pass B
    lstm_rec_kernel<<<64, 256, SM_TOTAL>>>(ws1_r, wc1_r, x_len, 342, 2);

    // CTC projection for both branches
    ctc_kernel<<<2736, 256>>>(ctc_w, ctc_b, out);

    // lens + close
    finalize_kernel<<<32, 256>>>(x_len, out);
}